// round 11
// baseline (speedup 1.0000x reference)
#include <cuda_runtime.h>
#include <math.h>
#include <stdint.h>

#define B_ 32
#define S_ 512
#define E_ 300
#define F_ 100
#define T_ 50
#define NCH 38
#define WTC 2496
#define CH_ 32
#define MSZ 3136          // 56x56 padded matrix

__device__ __align__(16) float g_em[B_ * S_ * T_];
__device__ float g_part[B_];
__device__ __align__(16) float g_wt2[NCH * WTC];
__device__ __align__(16) float g_fcw[56 * 104];
__device__ __align__(16) float g_E2[64 * 64];        // exp(trans), zero-pad
__device__ __align__(16) float g_Mc[B_ * CH_ * MSZ]; // chunk matrices [56][56]
__device__ __align__(16) float g_Mg[B_ * 4 * MSZ];   // group matrices [56][56]
__device__ float g_off[B_ * CH_];
__device__ float g_off2[B_ * 4];
__device__ unsigned g_cnt;

__device__ __forceinline__ float to_tf32(float x) {
    float r;
    asm("cvt.rna.tf32.f32 %0, %1;" : "=f"(r) : "f"(x));
    return r;
}
__device__ __forceinline__ int permk(int el) { return 2 * (el & 3) + (el >> 2); }

#define MMA_TF32_K8(d, a0, a1, a2, a3, b0, b1) \
    asm("mma.sync.aligned.m16n8k8.row.col.f32.tf32.tf32.f32 " \
        "{%0,%1,%2,%3}, {%4,%5,%6,%7}, {%8,%9}, {%0,%1,%2,%3};" \
        : "+f"(d[0]), "+f"(d[1]), "+f"(d[2]), "+f"(d[3]) \
        : "r"(a0), "r"(a1), "r"(a2), "r"(a3), "r"(b0), "r"(b1))

__global__ void k_nop() {}

// ---------------- Kernel 0: prepack conv W, fc W, exp(trans) ----------------
__global__ void k_wt(const float* __restrict__ cw, const float* __restrict__ fw,
                     const float* __restrict__ trans)
{
    int i = blockIdx.x * 256 + threadIdx.x;
    if (i < NCH * WTC) {
        int c = i / WTC, r = i - c * WTC;
        int f = r / 24, kk = r - f * 24;
        int dlt = kk >> 3, kp = kk & 7;
        int el = (kp >> 1) + 4 * (kp & 1);
        int e = c * 8 + el;
        float v = 0.f;
        if (f < F_ && e < E_) v = to_tf32(__ldg(&cw[f * 900 + e * 3 + dlt]));
        g_wt2[i] = v;
    }
    int j = i - NCH * WTC;
    if (j >= 0 && j < 56 * 104) {
        int t = j / 104, kf = j - t * 104;
        int f = (kf & ~7) + ((kf & 7) >> 1) + 4 * (kf & 1);
        float v = 0.f;
        if (t < T_ && f < F_) v = to_tf32(__ldg(&fw[t * F_ + f]));
        g_fcw[j] = v;
    }
    int iE = j - 56 * 104;
    if (iE >= 0 && iE < 64 * 64) {
        int a = iE >> 6, bcol = iE & 63;
        g_E2[iE] = (a < T_ && bcol < T_) ? to_tf32(expf(__ldg(&trans[a * T_ + bcol]))) : 0.f;
    }
}

// ---------------- Kernel 1: emissions (unchanged from R6) ----------------
__global__ __launch_bounds__(256, 2) void k_emissions(
    const int* __restrict__ x, const float* __restrict__ emb,
    const float* __restrict__ conv_b, const float* __restrict__ fc_b)
{
    __shared__ __align__(16) float sbuf[6656];
    __shared__ int sx[66];
    const int tid = threadIdx.x, b = blockIdx.y, s0 = blockIdx.x * 64;
    const int lane = tid & 31, w = tid >> 5, gq = lane >> 2, tq = lane & 3;

    if (tid < 66) {
        int sg = s0 - 1 + tid;
        sx[tid] = (sg >= 0 && sg < S_) ? x[b * S_ + sg] : -1;
    }
    __syncthreads();
    for (int idx = tid; idx < 528; idx += 256) {
        int r = idx >> 3, el = idx & 7, v = sx[r];
        sbuf[r * 8 + permk(el)] = (v >= 0) ? to_tf32(__ldg(&emb[v * E_ + el])) : 0.f;
    }
    for (int idx = tid; idx < 624; idx += 256)
        *(float4*)&sbuf[528 + idx * 4] = *(const float4*)&g_wt2[idx * 4];
    __syncthreads();

    const int m0 = 16 * (w & 3);
    const int nbase = (w < 4) ? 0 : 7, ntiles = (w < 4) ? 7 : 6;
    float acc[7][4];
    #pragma unroll
    for (int n = 0; n < 7; n++)
        #pragma unroll
        for (int q = 0; q < 4; q++) acc[n][q] = 0.f;

    float pa[3]; float4 pw[3];
    for (int c = 0; c < NCH; c++) {
        float* sT = sbuf + (c & 1) * 3024;
        float* Wt = sT + 528;
        if (c + 1 < NCH) {
            int e0 = (c + 1) * 8;
            #pragma unroll
            for (int r3 = 0; r3 < 3; r3++) {
                int idx = tid + 256 * r3;
                pa[r3] = 0.f;
                if (idx < 528) {
                    int v = sx[idx >> 3], e = e0 + (idx & 7);
                    if (v >= 0 && e < E_) pa[r3] = to_tf32(__ldg(&emb[v * E_ + e]));
                }
            }
            const float4* wsrc = (const float4*)&g_wt2[(c + 1) * WTC];
            #pragma unroll
            for (int r3 = 0; r3 < 3; r3++) {
                int idx = tid + 256 * r3;
                if (idx < 624) pw[r3] = __ldg(&wsrc[idx]);
            }
        }
        #pragma unroll
        for (int dlt = 0; dlt < 3; dlt++) {
            float2 aLo = *(const float2*)&sT[(m0 + dlt + gq) * 8 + 2 * tq];
            float2 aHi = *(const float2*)&sT[(m0 + dlt + gq + 8) * 8 + 2 * tq];
            #pragma unroll
            for (int n = 0; n < 7; n++)
                if (n < ntiles) {
                    float2 bb = *(const float2*)&Wt[(8 * (nbase + n) + gq) * 24 + dlt * 8 + 2 * tq];
                    MMA_TF32_K8(acc[n], __float_as_uint(aLo.x), __float_as_uint(aHi.x),
                                __float_as_uint(aLo.y), __float_as_uint(aHi.y),
                                __float_as_uint(bb.x), __float_as_uint(bb.y));
                }
        }
        __syncthreads();
        if (c + 1 < NCH) {
            float* sTn = sbuf + ((c + 1) & 1) * 3024;
            float* Wtn = sTn + 528;
            #pragma unroll
            for (int r3 = 0; r3 < 3; r3++) {
                int idx = tid + 256 * r3;
                if (idx < 528) sTn[(idx >> 3) * 8 + permk(idx & 7)] = pa[r3];
            }
            #pragma unroll
            for (int r3 = 0; r3 < 3; r3++) {
                int idx = tid + 256 * r3;
                if (idx < 624) *(float4*)&Wtn[idx * 4] = pw[r3];
            }
        }
        __syncthreads();
    }

    float* feat = sbuf;
    #pragma unroll
    for (int n = 0; n < 7; n++)
        if (n < ntiles) {
            int f = 8 * (nbase + n) + 2 * tq;
            float b0v = (f < F_) ? __ldg(&conv_b[f]) : 0.f;
            float b1v = (f + 1 < F_) ? __ldg(&conv_b[f + 1]) : 0.f;
            int k0 = (f >> 3) * 8 + permk(f & 7);
            int k1 = ((f + 1) >> 3) * 8 + permk((f + 1) & 7);
            feat[(m0 + gq) * 104 + k0]     = to_tf32(fmaxf(acc[n][0] + b0v, 0.f));
            feat[(m0 + gq) * 104 + k1]     = to_tf32(fmaxf(acc[n][1] + b1v, 0.f));
            feat[(m0 + gq + 8) * 104 + k0] = to_tf32(fmaxf(acc[n][2] + b0v, 0.f));
            feat[(m0 + gq + 8) * 104 + k1] = to_tf32(fmaxf(acc[n][3] + b1v, 0.f));
        }
    __syncthreads();

    const int mt = w & 3, nb2 = (w < 4) ? 0 : 4, nt2 = (w < 4) ? 4 : 3;
    float fa[4][4];
    #pragma unroll
    for (int n = 0; n < 4; n++)
        #pragma unroll
        for (int q = 0; q < 4; q++) fa[n][q] = 0.f;
    #pragma unroll
    for (int kb = 0; kb < 13; kb++) {
        float2 aLo = *(const float2*)&feat[(mt * 16 + gq) * 104 + kb * 8 + 2 * tq];
        float2 aHi = *(const float2*)&feat[(mt * 16 + gq + 8) * 104 + kb * 8 + 2 * tq];
        #pragma unroll
        for (int n = 0; n < 4; n++)
            if (n < nt2) {
                float2 bb = __ldg((const float2*)&g_fcw[(8 * (nb2 + n) + gq) * 104 + kb * 8 + 2 * tq]);
                MMA_TF32_K8(fa[n], __float_as_uint(aLo.x), __float_as_uint(aHi.x),
                            __float_as_uint(aLo.y), __float_as_uint(aHi.y),
                            __float_as_uint(bb.x), __float_as_uint(bb.y));
            }
    }
    #pragma unroll
    for (int n = 0; n < 4; n++)
        if (n < nt2) {
            int t = 8 * (nb2 + n) + 2 * tq;
            if (t < T_) {
                float bb0 = __ldg(&fc_b[t]), bb1 = __ldg(&fc_b[t + 1]);
                int s1 = s0 + mt * 16 + gq;
                *(float2*)&g_em[(b * S_ + s1) * T_ + t] = make_float2(fa[n][0] + bb0, fa[n][1] + bb1);
                *(float2*)&g_em[(b * S_ + s1 + 8) * T_ + t] = make_float2(fa[n][2] + bb0, fa[n][3] + bb1);
            }
        }
}

// ---------------- Kernel 2: chunk products; B in SMEM for occupancy ----------------
__global__ __launch_bounds__(128, 4) void k_chunk()
{
    __shared__ __align__(16) float2 sB[49 * 32];    // 12.25 KB, lane-indexed
    __shared__ __align__(8) float eemp[16][64];
    __shared__ float maxs[16];
    __shared__ float red[4];

    const int tid = threadIdx.x, c = blockIdx.x, b = blockIdx.y;
    const int lane = tid & 31, w = tid >> 5, gq = lane >> 2, tq = lane & 3;
    const int base = b * S_, sb = 1 + 16 * c;
    const int nst = (c == CH_ - 1) ? 15 : 16;

    // stage B fragments: sB[kb*7+n][lane] = (E2[8kb+tq][8n+ig], E2[8kb+tq+4][8n+ig])
    for (int idx = tid; idx < 1568; idx += 128) {
        int frag = idx >> 5, ln = idx & 31;
        int kb = frag / 7, n = frag - 7 * kb;
        int tql = ln & 3, gql = ln >> 2;
        int igl = (gql >> 1) + 4 * (gql & 1);
        sB[frag * 32 + ln] = make_float2(
            __ldg(&g_E2[(8 * kb + tql) * 64 + 8 * n + igl]),
            __ldg(&g_E2[(8 * kb + tql + 4) * 64 + 8 * n + igl]));
    }
    // stage eem (permuted layout) + per-step maxes
    for (int t = w; t < nst; t += 4) {
        float2 em = (lane < 25) ? __ldg((const float2*)&g_em[(base + sb + t) * T_ + 2 * lane])
                                : make_float2(0.f, 0.f);
        float m = (lane < 25) ? fmaxf(em.x, em.y) : -3.0e38f;
        #pragma unroll
        for (int o = 16; o; o >>= 1) m = fmaxf(m, __shfl_xor_sync(0xffffffffu, m, o));
        int j0 = 2 * lane, j1 = j0 + 1;
        float e0 = (lane < 25) ? __expf(em.x - m) : 0.f;
        float e1 = (lane < 25) ? __expf(em.y - m) : 0.f;
        eemp[t][8 * (j0 >> 3) + permk(j0 & 7)] = e0;
        eemp[t][8 * (j1 >> 3) + permk(j1 & 7)] = e1;
        if (lane == 0) maxs[t] = m;
    }
    __syncthreads();

    // init A = E2 * diag(eem0): rows 16w+gq, +8 (zero-padded rows/cols stay zero)
    float A[7][4];
    #pragma unroll
    for (int kb = 0; kb < 7; kb++) {
        float2 e2 = *(const float2*)&eemp[0][8 * kb + 2 * tq];
        int r0 = 16 * w + gq, r1 = r0 + 8;
        A[kb][0] = to_tf32(__ldg(&g_E2[r0 * 64 + 8 * kb + tq])     * e2.x);
        A[kb][1] = to_tf32(__ldg(&g_E2[r0 * 64 + 8 * kb + tq + 4]) * e2.y);
        A[kb][2] = to_tf32(__ldg(&g_E2[r1 * 64 + 8 * kb + tq])     * e2.x);
        A[kb][3] = to_tf32(__ldg(&g_E2[r1 * 64 + 8 * kb + tq + 4]) * e2.y);
    }

    for (int t = 1; t < nst; t++) {
        float acc[7][4];
        #pragma unroll
        for (int n = 0; n < 7; n++)
            #pragma unroll
            for (int q = 0; q < 4; q++) acc[n][q] = 0.f;
        #pragma unroll
        for (int kb = 0; kb < 7; kb++)
            #pragma unroll
            for (int n = 0; n < 7; n++) {
                float2 bb = sB[(kb * 7 + n) * 32 + lane];
                MMA_TF32_K8(acc[n],
                    __float_as_uint(A[kb][0]), __float_as_uint(A[kb][2]),
                    __float_as_uint(A[kb][1]), __float_as_uint(A[kb][3]),
                    __float_as_uint(bb.x), __float_as_uint(bb.y));
            }
        #pragma unroll
        for (int n = 0; n < 7; n++) {
            float2 e2 = *(const float2*)&eemp[t][8 * n + 2 * tq];
            A[n][0] = to_tf32(acc[n][0] * e2.x);
            A[n][1] = to_tf32(acc[n][1] * e2.y);
            A[n][2] = to_tf32(acc[n][2] * e2.x);
            A[n][3] = to_tf32(acc[n][3] * e2.y);
        }
    }

    // block max, normalize, write padded [56][56]
    float mx = 0.f;
    #pragma unroll
    for (int n = 0; n < 7; n++)
        #pragma unroll
        for (int q = 0; q < 4; q++) mx = fmaxf(mx, A[n][q]);
    #pragma unroll
    for (int o = 16; o; o >>= 1) mx = fmaxf(mx, __shfl_xor_sync(0xffffffffu, mx, o));
    if (lane == 0) red[w] = mx;
    __syncthreads();
    mx = fmaxf(fmaxf(red[0], red[1]), fmaxf(red[2], red[3]));
    float inv = 1.f / mx;

    float* mo = g_Mc + (b * CH_ + c) * MSZ;
    const int i0 = 16 * w + gq, i1 = i0 + 8;
    #pragma unroll
    for (int n = 0; n < 7; n++) {
        int j0 = 8 * n + tq, j1 = j0 + 4;
        mo[i0 * 56 + j0] = to_tf32(A[n][0] * inv);
        mo[i0 * 56 + j1] = to_tf32(A[n][1] * inv);
        if (i1 < 56) {
            mo[i1 * 56 + j0] = to_tf32(A[n][2] * inv);
            mo[i1 * 56 + j1] = to_tf32(A[n][3] * inv);
        }
    }
    if (tid == 0) {
        float off = __logf(mx);
        for (int t = 0; t < nst; t++) off += maxs[t];
        g_off[b * CH_ + c] = off;
    }
}

// ---------------- Kernel 2b: combine 8 chunk matrices -> 1 group matrix ----------------
__global__ void k_comb()
{
    __shared__ float red[4];
    const int tid = threadIdx.x, g = blockIdx.x, b = blockIdx.y;
    const int lane = tid & 31, w = tid >> 5, gq = lane >> 2, tq = lane & 3;
    const int ig = (gq >> 1) + 4 * (gq & 1);
    const int r0 = 16 * w + gq, r1 = r0 + 8;

    const float* M0 = g_Mc + (b * CH_ + 8 * g) * MSZ;
    float A[7][4];
    #pragma unroll
    for (int kb = 0; kb < 7; kb++) {
        A[kb][0] = __ldg(&M0[r0 * 56 + 8 * kb + tq]);
        A[kb][1] = __ldg(&M0[r0 * 56 + 8 * kb + tq + 4]);
        A[kb][2] = (r1 < 56) ? __ldg(&M0[r1 * 56 + 8 * kb + tq]) : 0.f;
        A[kb][3] = (r1 < 56) ? __ldg(&M0[r1 * 56 + 8 * kb + tq + 4]) : 0.f;
    }

    for (int t = 1; t < 8; t++) {
        const float* Mt = g_Mc + (b * CH_ + 8 * g + t) * MSZ;
        float2 Bf[49];
        #pragma unroll
        for (int kb = 0; kb < 7; kb++)
            #pragma unroll
            for (int n = 0; n < 7; n++)
                Bf[kb * 7 + n] = make_float2(
                    __ldg(&Mt[(8 * kb + tq) * 56 + 8 * n + ig]),
                    __ldg(&Mt[(8 * kb + tq + 4) * 56 + 8 * n + ig]));
        float acc[7][4];
        #pragma unroll
        for (int n = 0; n < 7; n++)
            #pragma unroll
            for (int q = 0; q < 4; q++) acc[n][q] = 0.f;
        #pragma unroll
        for (int kb = 0; kb < 7; kb++)
            #pragma unroll
            for (int n = 0; n < 7; n++)
                MMA_TF32_K8(acc[n],
                    __float_as_uint(A[kb][0]), __float_as_uint(A[kb][2]),
                    __float_as_uint(A[kb][1]), __float_as_uint(A[kb][3]),
                    __float_as_uint(Bf[kb * 7 + n].x), __float_as_uint(Bf[kb * 7 + n].y));
        #pragma unroll
        for (int n = 0; n < 7; n++)
            #pragma unroll
            for (int q = 0; q < 4; q++) A[n][q] = to_tf32(acc[n][q]);
    }

    float mx = 0.f;
    #pragma unroll
    for (int n = 0; n < 7; n++)
        #pragma unroll
        for (int q = 0; q < 4; q++) mx = fmaxf(mx, A[n][q]);
    #pragma unroll
    for (int o = 16; o; o >>= 1) mx = fmaxf(mx, __shfl_xor_sync(0xffffffffu, mx, o));
    if (lane == 0) red[w] = mx;
    __syncthreads();
    mx = fmaxf(fmaxf(red[0], red[1]), fmaxf(red[2], red[3]));
    float inv = 1.f / mx;

    float* mo = g_Mg + (b * 4 + g) * MSZ;
    #pragma unroll
    for (int n = 0; n < 7; n++) {
        int j0 = 8 * n + tq, j1 = j0 + 4;
        mo[r0 * 56 + j0] = A[n][0] * inv;
        mo[r0 * 56 + j1] = A[n][1] * inv;
        if (r1 < 56) {
            mo[r1 * 56 + j0] = A[n][2] * inv;
            mo[r1 * 56 + j1] = A[n][3] * inv;
        }
    }
    if (tid == 0) {
        float off = __logf(mx);
        for (int t = 0; t < 8; t++) off += g_off[b * CH_ + 8 * g + t];
        g_off2[b * 4 + g] = off;
    }
}

// ---------------- Kernel 3: per-batch finish (4 group matvecs) ----------------
__global__ __launch_bounds__(128) void k_final(
    const int* __restrict__ tags, const float* __restrict__ start_trans,
    const float* __restrict__ end_trans, const float* __restrict__ trans,
    float* __restrict__ out)
{
    __shared__ float pbuf[52];
    __shared__ float part[4][64];
    __shared__ float redn[4];

    const int tid = threadIdx.x, lane = tid & 31, w = tid >> 5;
    const int b = blockIdx.x, base = b * S_;
    const bool act = lane < 25;
    const int j0 = 2 * lane, j1 = j0 + 1;

    const int* tg = tags + base;
    float local = 0.f;
    for (int s = tid; s < S_; s += 128) {
        int t = __ldg(&tg[s]);
        local += __ldg(&g_em[(base + s) * T_ + t]);
        if (s < S_ - 1) local += __ldg(&trans[t * T_ + __ldg(&tg[s + 1])]);
    }
    #pragma unroll
    for (int o = 16; o; o >>= 1) local += __shfl_xor_sync(0xffffffffu, local, o);
    if (lane == 0) redn[w] = local;

    float al0 = -3.0e38f, al1 = -3.0e38f;
    if (act) {
        float2 e0 = *(const float2*)&g_em[base * T_ + j0];
        al0 = __ldg(&start_trans[j0]) + e0.x;
        al1 = __ldg(&start_trans[j1]) + e0.y;
    }
    float mv = fmaxf(al0, al1);
    #pragma unroll
    for (int o = 16; o; o >>= 1) mv = fmaxf(mv, __shfl_xor_sync(0xffffffffu, mv, o));
    float off = mv;
    float p0 = act ? __expf(al0 - mv) : 0.f;
    float p1 = act ? __expf(al1 - mv) : 0.f;
    if (w == 0 && act) *(float2*)&pbuf[j0] = make_float2(p0, p1);
    __syncthreads();

    float2 Mreg[13], Mnext[13];
    #pragma unroll
    for (int r = 0; r < 13; r++) {
        int i = 13 * w + r;
        Mreg[r] = (act && i < T_) ? __ldg((const float2*)&g_Mg[(b * 4) * MSZ + i * 56 + j0])
                                  : make_float2(0.f, 0.f);
    }

    for (int c = 0; c < 4; c++) {
        #pragma unroll
        for (int r = 0; r < 13; r++) {
            int i = 13 * w + r;
            Mnext[r] = (c + 1 < 4 && act && i < T_)
                ? __ldg((const float2*)&g_Mg[(b * 4 + c + 1) * MSZ + i * 56 + j0])
                : make_float2(0.f, 0.f);
        }
        float n0 = 0.f, n1 = 0.f;
        #pragma unroll
        for (int r = 0; r < 13; r++) {
            int i = 13 * w + r;
            if (i < T_) {
                float pi = pbuf[i];
                n0 += pi * Mreg[r].x;
                n1 += pi * Mreg[r].y;
            }
        }
        part[w][j0] = n0;
        part[w][j1] = n1;
        __syncthreads();
        n0 = part[0][j0] + part[1][j0] + part[2][j0] + part[3][j0];
        n1 = part[0][j1] + part[1][j1] + part[2][j1] + part[3][j1];
        float mxv = act ? fmaxf(n0, n1) : 0.f;
        #pragma unroll
        for (int o = 16; o; o >>= 1) mxv = fmaxf(mxv, __shfl_xor_sync(0xffffffffu, mxv, o));
        off += __ldg(&g_off2[b * 4 + c]) + __logf(mxv);
        float iv = 1.f / mxv;
        p0 = n0 * iv;
        p1 = n1 * iv;
        if (w == 0 && act) *(float2*)&pbuf[j0] = make_float2(p0, p1);
        __syncthreads();
        #pragma unroll
        for (int r = 0; r < 13; r++) Mreg[r] = Mnext[r];
    }

    if (w == 0) {
        float s_num = redn[0] + redn[1] + redn[2] + redn[3]
                    + __ldg(&start_trans[tg[0]]) + __ldg(&end_trans[tg[S_ - 1]]);
        float av = act ? p0 * __expf(__ldg(&end_trans[j0])) + p1 * __expf(__ldg(&end_trans[j1])) : 0.f;
        #pragma unroll
        for (int o = 16; o; o >>= 1) av += __shfl_xor_sync(0xffffffffu, av, o);
        if (lane == 0) g_part[b] = (off + logf(av)) - s_num;

        unsigned isl = 0;
        if (lane == 0) {
            __threadfence();
            unsigned prev = atomicAdd(&g_cnt, 1u);
            isl = (prev == B_ - 1) ? 1u : 0u;
        }
        isl = __shfl_sync(0xffffffffu, isl, 0);
        if (isl) {
            __threadfence();
            float v = g_part[lane];
            #pragma unroll
            for (int o = 16; o; o >>= 1) v += __shfl_xor_sync(0xffffffffu, v, o);
            if (lane == 0) { out[0] = v; g_cnt = 0u; }
        }
    }
}

extern "C" void kernel_launch(void* const* d_in, const int* in_sizes, int n_in,
                              void* d_out, int out_size)
{
    const int*   x           = (const int*)  d_in[0];
    const int*   tags        = (const int*)  d_in[1];
    const float* emb         = (const float*)d_in[2];
    const float* conv_w      = (const float*)d_in[3];
    const float* conv_b      = (const float*)d_in[4];
    const float* fc_w        = (const float*)d_in[5];
    const float* fc_b        = (const float*)d_in[6];
    const float* start_trans = (const float*)d_in[7];
    const float* end_trans   = (const float*)d_in[8];
    const float* trans       = (const float*)d_in[9];
    float* out = (float*)d_out;

    int nwt = NCH * WTC + 56 * 104 + 64 * 64;
    k_nop<<<1, 1>>>();   // capture idx 3 = k_chunk
    k_wt<<<(nwt + 255) / 256, 256>>>(conv_w, fc_w, trans);
    k_emissions<<<dim3(S_ / 64, B_), 256>>>(x, emb, conv_b, fc_b);
    k_chunk<<<dim3(CH_, B_), 128>>>();
    k_comb<<<dim3(4, B_), 128>>>();
    k_final<<<B_, 128>>>(tags, start_trans, end_trans, trans, out);
}

// round 13
// speedup vs baseline: 1.4568x; 1.4568x over previous
#include <cuda_runtime.h>
#include <cuda_bf16.h>
#include <math.h>
#include <stdint.h>

#define B_ 32
#define S_ 512
#define E_ 300
#define F_ 100
#define T_ 50
#define NCH 38
#define WTC 2496
#define CH2 16            // CRF chunks per batch (32 steps each)
#define MSZ 3136          // 56x56 padded matrix

__device__ __align__(16) float g_em[B_ * S_ * T_];
__device__ float g_part[B_];
__device__ __align__(16) float g_wt2[NCH * WTC];
__device__ __align__(16) float g_fcw[56 * 104];
__device__ __align__(16) float g_E2[64 * 64];          // exp(trans), zero-pad
__device__ __align__(16) float g_Mc[B_ * CH2 * MSZ];   // chunk matrices [56][56]
__device__ float g_off[B_ * CH2];
__device__ unsigned g_bcnt[B_];
__device__ unsigned g_cnt;

__device__ __forceinline__ float to_tf32(float x) {
    float r;
    asm("cvt.rna.tf32.f32 %0, %1;" : "=f"(r) : "f"(x));
    return r;
}
__device__ __forceinline__ int permk(int el) { return 2 * (el & 3) + (el >> 2); }

#define MMA_TF32_K8(d, a0, a1, a2, a3, b0, b1) \
    asm("mma.sync.aligned.m16n8k8.row.col.f32.tf32.tf32.f32 " \
        "{%0,%1,%2,%3}, {%4,%5,%6,%7}, {%8,%9}, {%0,%1,%2,%3};" \
        : "+f"(d[0]), "+f"(d[1]), "+f"(d[2]), "+f"(d[3]) \
        : "r"(a0), "r"(a1), "r"(a2), "r"(a3), "r"(b0), "r"(b1))

// bf16 m16n8k16: A 4x b32 (bf16x2), B 2x b32, D/C 4x f32
#define MMA_BF16_K16(d, a0, a1, a2, a3, b0, b1) \
    asm("mma.sync.aligned.m16n8k16.row.col.f32.bf16.bf16.f32 " \
        "{%0,%1,%2,%3}, {%4,%5,%6,%7}, {%8,%9}, {%0,%1,%2,%3};" \
        : "+f"(d[0]), "+f"(d[1]), "+f"(d[2]), "+f"(d[3]) \
        : "r"(a0), "r"(a1), "r"(a2), "r"(a3), "r"(b0), "r"(b1))

// pack (lo, hi) f32 -> bf16x2 register (cvt dst = {hi=%1, lo=%2})
#define PACKBF(d, lo, hi) \
    asm("cvt.rn.bf16x2.f32 %0, %1, %2;" : "=r"(d) : "f"(hi), "f"(lo))

__device__ __forceinline__ float2 unpbf(uint32_t v) {
    __nv_bfloat162 h = *(__nv_bfloat162*)&v;
    return make_float2(__low2float(h), __high2float(h));
}

__global__ void k_nop() {}

// ---------------- Kernel 0: prepack conv W, fc W, exp(trans) ----------------
__global__ void k_wt(const float* __restrict__ cw, const float* __restrict__ fw,
                     const float* __restrict__ trans)
{
    int i = blockIdx.x * 256 + threadIdx.x;
    if (i < NCH * WTC) {
        int c = i / WTC, r = i - c * WTC;
        int f = r / 24, kk = r - f * 24;
        int dlt = kk >> 3, kp = kk & 7;
        int el = (kp >> 1) + 4 * (kp & 1);
        int e = c * 8 + el;
        float v = 0.f;
        if (f < F_ && e < E_) v = to_tf32(__ldg(&cw[f * 900 + e * 3 + dlt]));
        g_wt2[i] = v;
    }
    int j = i - NCH * WTC;
    if (j >= 0 && j < 56 * 104) {
        int t = j / 104, kf = j - t * 104;
        int f = (kf & ~7) + ((kf & 7) >> 1) + 4 * (kf & 1);
        float v = 0.f;
        if (t < T_ && f < F_) v = to_tf32(__ldg(&fw[t * F_ + f]));
        g_fcw[j] = v;
    }
    int iE = j - 56 * 104;
    if (iE >= 0 && iE < 64 * 64) {
        int a = iE >> 6, bcol = iE & 63;
        g_E2[iE] = (a < T_ && bcol < T_) ? expf(__ldg(&trans[a * T_ + bcol])) : 0.f;
    }
}

// ---------------- Kernel 1: emissions (unchanged, validated) ----------------
__global__ __launch_bounds__(256, 2) void k_emissions(
    const int* __restrict__ x, const float* __restrict__ emb,
    const float* __restrict__ conv_b, const float* __restrict__ fc_b)
{
    __shared__ __align__(16) float sbuf[6656];
    __shared__ int sx[66];
    const int tid = threadIdx.x, b = blockIdx.y, s0 = blockIdx.x * 64;
    const int lane = tid & 31, w = tid >> 5, gq = lane >> 2, tq = lane & 3;

    if (tid < 66) {
        int sg = s0 - 1 + tid;
        sx[tid] = (sg >= 0 && sg < S_) ? x[b * S_ + sg] : -1;
    }
    __syncthreads();
    for (int idx = tid; idx < 528; idx += 256) {
        int r = idx >> 3, el = idx & 7, v = sx[r];
        sbuf[r * 8 + permk(el)] = (v >= 0) ? to_tf32(__ldg(&emb[v * E_ + el])) : 0.f;
    }
    for (int idx = tid; idx < 624; idx += 256)
        *(float4*)&sbuf[528 + idx * 4] = *(const float4*)&g_wt2[idx * 4];
    __syncthreads();

    const int m0 = 16 * (w & 3);
    const int nbase = (w < 4) ? 0 : 7, ntiles = (w < 4) ? 7 : 6;
    float acc[7][4];
    #pragma unroll
    for (int n = 0; n < 7; n++)
        #pragma unroll
        for (int q = 0; q < 4; q++) acc[n][q] = 0.f;

    float pa[3]; float4 pw[3];
    for (int c = 0; c < NCH; c++) {
        float* sT = sbuf + (c & 1) * 3024;
        float* Wt = sT + 528;
        if (c + 1 < NCH) {
            int e0 = (c + 1) * 8;
            #pragma unroll
            for (int r3 = 0; r3 < 3; r3++) {
                int idx = tid + 256 * r3;
                pa[r3] = 0.f;
                if (idx < 528) {
                    int v = sx[idx >> 3], e = e0 + (idx & 7);
                    if (v >= 0 && e < E_) pa[r3] = to_tf32(__ldg(&emb[v * E_ + e]));
                }
            }
            const float4* wsrc = (const float4*)&g_wt2[(c + 1) * WTC];
            #pragma unroll
            for (int r3 = 0; r3 < 3; r3++) {
                int idx = tid + 256 * r3;
                if (idx < 624) pw[r3] = __ldg(&wsrc[idx]);
            }
        }
        #pragma unroll
        for (int dlt = 0; dlt < 3; dlt++) {
            float2 aLo = *(const float2*)&sT[(m0 + dlt + gq) * 8 + 2 * tq];
            float2 aHi = *(const float2*)&sT[(m0 + dlt + gq + 8) * 8 + 2 * tq];
            #pragma unroll
            for (int n = 0; n < 7; n++)
                if (n < ntiles) {
                    float2 bb = *(const float2*)&Wt[(8 * (nbase + n) + gq) * 24 + dlt * 8 + 2 * tq];
                    MMA_TF32_K8(acc[n], __float_as_uint(aLo.x), __float_as_uint(aHi.x),
                                __float_as_uint(aLo.y), __float_as_uint(aHi.y),
                                __float_as_uint(bb.x), __float_as_uint(bb.y));
                }
        }
        __syncthreads();
        if (c + 1 < NCH) {
            float* sTn = sbuf + ((c + 1) & 1) * 3024;
            float* Wtn = sTn + 528;
            #pragma unroll
            for (int r3 = 0; r3 < 3; r3++) {
                int idx = tid + 256 * r3;
                if (idx < 528) sTn[(idx >> 3) * 8 + permk(idx & 7)] = pa[r3];
            }
            #pragma unroll
            for (int r3 = 0; r3 < 3; r3++) {
                int idx = tid + 256 * r3;
                if (idx < 624) *(float4*)&Wtn[idx * 4] = pw[r3];
            }
        }
        __syncthreads();
    }

    float* feat = sbuf;
    #pragma unroll
    for (int n = 0; n < 7; n++)
        if (n < ntiles) {
            int f = 8 * (nbase + n) + 2 * tq;
            float b0v = (f < F_) ? __ldg(&conv_b[f]) : 0.f;
            float b1v = (f + 1 < F_) ? __ldg(&conv_b[f + 1]) : 0.f;
            int k0 = (f >> 3) * 8 + permk(f & 7);
            int k1 = ((f + 1) >> 3) * 8 + permk((f + 1) & 7);
            feat[(m0 + gq) * 104 + k0]     = to_tf32(fmaxf(acc[n][0] + b0v, 0.f));
            feat[(m0 + gq) * 104 + k1]     = to_tf32(fmaxf(acc[n][1] + b1v, 0.f));
            feat[(m0 + gq + 8) * 104 + k0] = to_tf32(fmaxf(acc[n][2] + b0v, 0.f));
            feat[(m0 + gq + 8) * 104 + k1] = to_tf32(fmaxf(acc[n][3] + b1v, 0.f));
        }
    __syncthreads();

    const int mt = w & 3, nb2 = (w < 4) ? 0 : 4, nt2 = (w < 4) ? 4 : 3;
    float fa[4][4];
    #pragma unroll
    for (int n = 0; n < 4; n++)
        #pragma unroll
        for (int q = 0; q < 4; q++) fa[n][q] = 0.f;
    #pragma unroll
    for (int kb = 0; kb < 13; kb++) {
        float2 aLo = *(const float2*)&feat[(mt * 16 + gq) * 104 + kb * 8 + 2 * tq];
        float2 aHi = *(const float2*)&feat[(mt * 16 + gq + 8) * 104 + kb * 8 + 2 * tq];
        #pragma unroll
        for (int n = 0; n < 4; n++)
            if (n < nt2) {
                float2 bb = __ldg((const float2*)&g_fcw[(8 * (nb2 + n) + gq) * 104 + kb * 8 + 2 * tq]);
                MMA_TF32_K8(fa[n], __float_as_uint(aLo.x), __float_as_uint(aHi.x),
                            __float_as_uint(aLo.y), __float_as_uint(aHi.y),
                            __float_as_uint(bb.x), __float_as_uint(bb.y));
            }
    }
    #pragma unroll
    for (int n = 0; n < 4; n++)
        if (n < nt2) {
            int t = 8 * (nb2 + n) + 2 * tq;
            if (t < T_) {
                float bb0 = __ldg(&fc_b[t]), bb1 = __ldg(&fc_b[t + 1]);
                int s1 = s0 + mt * 16 + gq;
                *(float2*)&g_em[(b * S_ + s1) * T_ + t] = make_float2(fa[n][0] + bb0, fa[n][1] + bb1);
                *(float2*)&g_em[(b * S_ + s1 + 8) * T_ + t] = make_float2(fa[n][2] + bb0, fa[n][3] + bb1);
            }
        }
}

// ---------------- Kernel 2: bf16 chunk products + fused per-batch finish ----------------
__global__ __launch_bounds__(128, 4) void k_chunk(
    const int* __restrict__ tags, const float* __restrict__ start_trans,
    const float* __restrict__ end_trans, const float* __restrict__ trans,
    float* __restrict__ out)
{
    __shared__ __align__(16) float eemp[32][64];
    __shared__ __align__(16) float pbuf[52];
    __shared__ __align__(16) float part[4][64];
    __shared__ __align__(16) float maxs[32];
    __shared__ __align__(16) float red[4];
    __shared__ __align__(16) float redn[4];
    __shared__ int sflag;

    const int tid = threadIdx.x, c = blockIdx.x, b = blockIdx.y;
    const int lane = tid & 31, w = tid >> 5, gq = lane >> 2, tq = lane & 3;
    const int base = b * S_, sb = 1 + 32 * c;
    const int nst = (c == CH2 - 1) ? 31 : 32;
    const int r0 = 16 * w + gq, r1 = r0 + 8;

    for (int t = w; t < nst; t += 4) {
        float2 em = (lane < 25) ? __ldg((const float2*)&g_em[(base + sb + t) * T_ + 2 * lane])
                                : make_float2(0.f, 0.f);
        float m = (lane < 25) ? fmaxf(em.x, em.y) : -3.0e38f;
        #pragma unroll
        for (int o = 16; o; o >>= 1) m = fmaxf(m, __shfl_xor_sync(0xffffffffu, m, o));
        float e0 = (lane < 25) ? __expf(em.x - m) : 0.f;
        float e1 = (lane < 25) ? __expf(em.y - m) : 0.f;
        *(float2*)&eemp[t][2 * lane] = make_float2(e0, e1);
        if (lane == 0) maxs[t] = m;
    }
    __syncthreads();

    uint32_t Bv[4][7][2];
    #pragma unroll
    for (int kb = 0; kb < 4; kb++)
        #pragma unroll
        for (int n = 0; n < 7; n++) {
            int col = 8 * n + gq;
            PACKBF(Bv[kb][n][0], __ldg(&g_E2[(16 * kb + 2 * tq) * 64 + col]),
                                 __ldg(&g_E2[(16 * kb + 2 * tq + 1) * 64 + col]));
            PACKBF(Bv[kb][n][1], __ldg(&g_E2[(16 * kb + 8 + 2 * tq) * 64 + col]),
                                 __ldg(&g_E2[(16 * kb + 9 + 2 * tq) * 64 + col]));
        }

    uint32_t A[4][4];
    #pragma unroll
    for (int kb = 0; kb < 4; kb++) {
        int c0 = 16 * kb + 2 * tq, c8 = c0 + 8;
        float2 eA = *(const float2*)&eemp[0][c0];
        float2 eB = *(const float2*)&eemp[0][c8];
        PACKBF(A[kb][0], __ldg(&g_E2[r0 * 64 + c0]) * eA.x, __ldg(&g_E2[r0 * 64 + c0 + 1]) * eA.y);
        PACKBF(A[kb][1], __ldg(&g_E2[r1 * 64 + c0]) * eA.x, __ldg(&g_E2[r1 * 64 + c0 + 1]) * eA.y);
        PACKBF(A[kb][2], __ldg(&g_E2[r0 * 64 + c8]) * eB.x, __ldg(&g_E2[r0 * 64 + c8 + 1]) * eB.y);
        PACKBF(A[kb][3], __ldg(&g_E2[r1 * 64 + c8]) * eB.x, __ldg(&g_E2[r1 * 64 + c8 + 1]) * eB.y);
    }

    float logren = 0.f;
    float acc[7][4];
    for (int t = 1; t < nst; t++) {
        #pragma unroll
        for (int n = 0; n < 7; n++)
            #pragma unroll
            for (int q = 0; q < 4; q++) acc[n][q] = 0.f;
        #pragma unroll
        for (int kb = 0; kb < 4; kb++)
            #pragma unroll
            for (int n = 0; n < 7; n++)
                MMA_BF16_K16(acc[n], A[kb][0], A[kb][1], A[kb][2], A[kb][3],
                             Bv[kb][n][0], Bv[kb][n][1]);
        #pragma unroll
        for (int n = 0; n < 7; n++) {
            float2 e2 = *(const float2*)&eemp[t][8 * n + 2 * tq];
            acc[n][0] *= e2.x; acc[n][1] *= e2.y;
            acc[n][2] *= e2.x; acc[n][3] *= e2.y;
        }
        if (t == 10 || t == 20) {
            float mx = 0.f;
            #pragma unroll
            for (int n = 0; n < 7; n++)
                #pragma unroll
                for (int q = 0; q < 4; q++) mx = fmaxf(mx, acc[n][q]);
            #pragma unroll
            for (int o = 16; o; o >>= 1) mx = fmaxf(mx, __shfl_xor_sync(0xffffffffu, mx, o));
            if (lane == 0) red[w] = mx;
            __syncthreads();
            mx = fmaxf(fmaxf(red[0], red[1]), fmaxf(red[2], red[3]));
            __syncthreads();
            float iv = 1.f / mx;
            logren += __logf(mx);
            #pragma unroll
            for (int n = 0; n < 7; n++)
                #pragma unroll
                for (int q = 0; q < 4; q++) acc[n][q] *= iv;
        }
        #pragma unroll
        for (int n = 0; n < 7; n++) {
            int kb = n >> 1, h = n & 1;
            PACKBF(A[kb][2 * h],     acc[n][0], acc[n][1]);
            PACKBF(A[kb][2 * h + 1], acc[n][2], acc[n][3]);
        }
        A[3][2] = 0u; A[3][3] = 0u;
    }

    float Fv[7][4];
    #pragma unroll
    for (int n = 0; n < 7; n++) {
        int kb = n >> 1, h = n & 1;
        float2 lo = unpbf(A[kb][2 * h]), hi = unpbf(A[kb][2 * h + 1]);
        Fv[n][0] = lo.x; Fv[n][1] = lo.y; Fv[n][2] = hi.x; Fv[n][3] = hi.y;
    }
    float mx = 0.f;
    #pragma unroll
    for (int n = 0; n < 7; n++)
        #pragma unroll
        for (int q = 0; q < 4; q++) mx = fmaxf(mx, Fv[n][q]);
    #pragma unroll
    for (int o = 16; o; o >>= 1) mx = fmaxf(mx, __shfl_xor_sync(0xffffffffu, mx, o));
    if (lane == 0) red[w] = mx;
    __syncthreads();
    mx = fmaxf(fmaxf(red[0], red[1]), fmaxf(red[2], red[3]));
    float inv = 1.f / mx;

    float* mo = g_Mc + (b * CH2 + c) * MSZ;
    #pragma unroll
    for (int n = 0; n < 7; n++) {
        int j0 = 8 * n + 2 * tq;
        mo[r0 * 56 + j0]     = Fv[n][0] * inv;
        mo[r0 * 56 + j0 + 1] = Fv[n][1] * inv;
        if (r1 < 56) {
            mo[r1 * 56 + j0]     = Fv[n][2] * inv;
            mo[r1 * 56 + j0 + 1] = Fv[n][3] * inv;
        }
    }
    if (tid == 0) {
        float off = logren + __logf(mx);
        for (int t = 0; t < nst; t++) off += maxs[t];
        g_off[b * CH2 + c] = off;
    }

    __syncthreads();
    if (tid == 0) {
        __threadfence();
        unsigned prev = atomicAdd(&g_bcnt[b], 1u);
        sflag = (prev == CH2 - 1) ? 1 : 0;
    }
    __syncthreads();
    if (!sflag) return;
    __threadfence();

    const int* tg = tags + base;
    const bool act = lane < 25;
    const int j0 = 2 * lane, j1 = j0 + 1;

    float local = 0.f;
    for (int s = tid; s < S_; s += 128) {
        int t = __ldg(&tg[s]);
        local += __ldg(&g_em[(base + s) * T_ + t]);
        if (s < S_ - 1) local += __ldg(&trans[t * T_ + __ldg(&tg[s + 1])]);
    }
    #pragma unroll
    for (int o = 16; o; o >>= 1) local += __shfl_xor_sync(0xffffffffu, local, o);
    if (lane == 0) redn[w] = local;

    float al0 = -3.0e38f, al1 = -3.0e38f;
    if (act) {
        float2 e0 = *(const float2*)&g_em[base * T_ + j0];
        al0 = __ldg(&start_trans[j0]) + e0.x;
        al1 = __ldg(&start_trans[j1]) + e0.y;
    }
    float mv = fmaxf(al0, al1);
    #pragma unroll
    for (int o = 16; o; o >>= 1) mv = fmaxf(mv, __shfl_xor_sync(0xffffffffu, mv, o));
    float off2 = mv;
    float p0 = act ? __expf(al0 - mv) : 0.f;
    float p1 = act ? __expf(al1 - mv) : 0.f;
    if (w == 0 && act) *(float2*)&pbuf[j0] = make_float2(p0, p1);
    __syncthreads();

    float2 Mreg[13], Mnext[13];
    #pragma unroll
    for (int r = 0; r < 13; r++) {
        int i = 13 * w + r;
        Mreg[r] = (act && i < T_) ? __ldg((const float2*)&g_Mc[(b * CH2) * MSZ + i * 56 + j0])
                                  : make_float2(0.f, 0.f);
    }
    for (int cc = 0; cc < CH2; cc++) {
        #pragma unroll
        for (int r = 0; r < 13; r++) {
            int i = 13 * w + r;
            Mnext[r] = (cc + 1 < CH2 && act && i < T_)
                ? __ldg((const float2*)&g_Mc[(b * CH2 + cc + 1) * MSZ + i * 56 + j0])
                : make_float2(0.f, 0.f);
        }
        float n0 = 0.f, n1 = 0.f;
        #pragma unroll
        for (int r = 0; r < 13; r++) {
            int i = 13 * w + r;
            if (i < T_) {
                float pi = pbuf[i];
                n0 += pi * Mreg[r].x;
                n1 += pi * Mreg[r].y;
            }
        }
        part[w][j0] = n0;
        part[w][j1] = n1;
        __syncthreads();
        n0 = part[0][j0] + part[1][j0] + part[2][j0] + part[3][j0];
        n1 = part[0][j1] + part[1][j1] + part[2][j1] + part[3][j1];
        float mxv = act ? fmaxf(n0, n1) : 0.f;
        #pragma unroll
        for (int o = 16; o; o >>= 1) mxv = fmaxf(mxv, __shfl_xor_sync(0xffffffffu, mxv, o));
        off2 += __ldg(&g_off[b * CH2 + cc]) + __logf(mxv);
        float iv = 1.f / mxv;
        p0 = n0 * iv;
        p1 = n1 * iv;
        if (w == 0 && act) *(float2*)&pbuf[j0] = make_float2(p0, p1);
        __syncthreads();
        #pragma unroll
        for (int r = 0; r < 13; r++) Mreg[r] = Mnext[r];
    }

    if (w == 0) {
        float s_num = redn[0] + redn[1] + redn[2] + redn[3]
                    + __ldg(&start_trans[tg[0]]) + __ldg(&end_trans[tg[S_ - 1]]);
        float av = act ? p0 * __expf(__ldg(&end_trans[j0])) + p1 * __expf(__ldg(&end_trans[j1])) : 0.f;
        #pragma unroll
        for (int o = 16; o; o >>= 1) av += __shfl_xor_sync(0xffffffffu, av, o);
        if (lane == 0) {
            g_part[b] = (off2 + logf(av)) - s_num;
            g_bcnt[b] = 0u;
        }
        unsigned isl = 0;
        if (lane == 0) {
            __threadfence();
            unsigned prev = atomicAdd(&g_cnt, 1u);
            isl = (prev == B_ - 1) ? 1u : 0u;
        }
        isl = __shfl_sync(0xffffffffu, isl, 0);
        if (isl) {
            __threadfence();
            float v = g_part[lane];
            #pragma unroll
            for (int o = 16; o; o >>= 1) v += __shfl_xor_sync(0xffffffffu, v, o);
            if (lane == 0) { out[0] = v; g_cnt = 0u; }
        }
    }
}

extern "C" void kernel_launch(void* const* d_in, const int* in_sizes, int n_in,
                              void* d_out, int out_size)
{
    const int*   x           = (const int*)  d_in[0];
    const int*   tags        = (const int*)  d_in[1];
    const float* emb         = (const float*)d_in[2];
    const float* conv_w      = (const float*)d_in[3];
    const float* conv_b      = (const float*)d_in[4];
    const float* fc_w        = (const float*)d_in[5];
    const float* fc_b        = (const float*)d_in[6];
    const float* start_trans = (const float*)d_in[7];
    const float* end_trans   = (const float*)d_in[8];
    const float* trans       = (const float*)d_in[9];
    float* out = (float*)d_out;

    int nwt = NCH * WTC + 56 * 104 + 64 * 64;
    k_nop<<<1, 1>>>();   // capture idx 3 = k_chunk
    k_wt<<<(nwt + 255) / 256, 256>>>(conv_w, fc_w, trans);
    k_emissions<<<dim3(S_ / 64, B_), 256>>>(x, emb, conv_b, fc_b);
    k_chunk<<<dim3(CH2, B_), 128>>>(tags, start_trans, end_trans, trans, out);
}